// round 4
// baseline (speedup 1.0000x reference)
#include <cuda_runtime.h>
#include <cuda_bf16.h>

// Problem constants
#define B_   16
#define S_   4096
#define C_   1024
#define H_   16
#define D_   64
#define SPLIT 16                      // S-chunks for attention
#define KSPLIT 16                     // k-chunks for the w0 GEMM
#define NBH  (B_ * H_)                // 256
#define ROWS_PER_CHUNK (S_ / SPLIT)   // 256

// Scratch (device globals; no allocation allowed)
__device__ float g_qn[C_];                         // normalized*scaled query
__device__ float g_pacc[NBH * SPLIT * D_];         // partial weighted-V sums
__device__ float g_pl[NBH * SPLIT];                // partial exp-sums
__device__ float g_A[B_ * C_];                     // attention output, multihead-unshaped
__device__ float g_Ypart[KSPLIT * B_ * C_];        // GEMM k-chunk partials

// ---------------------------------------------------------------------------
// Kernel 1: qn = q / ||q|| * (1/sqrt(d))
// ---------------------------------------------------------------------------
__global__ void qnorm_kernel(const float* __restrict__ q) {
    __shared__ float red[8];
    __shared__ float s_scale;
    int tid = threadIdx.x;                 // 256 threads, 4 floats each
    float4 qv = ((const float4*)q)[tid];
    float s = qv.x*qv.x + qv.y*qv.y + qv.z*qv.z + qv.w*qv.w;
    #pragma unroll
    for (int o = 16; o; o >>= 1) s += __shfl_xor_sync(0xFFFFFFFFu, s, o);
    if ((tid & 31) == 0) red[tid >> 5] = s;
    __syncthreads();
    if (tid == 0) {
        float t = 0.f;
        #pragma unroll
        for (int w = 0; w < 8; w++) t += red[w];
        s_scale = rsqrtf(t) * 0.125f;      // 1/||q|| * 1/sqrt(64)
    }
    __syncthreads();
    float sc = s_scale;
    float4 o;
    o.x = qv.x * sc; o.y = qv.y * sc; o.z = qv.z * sc; o.w = qv.w * sc;
    ((float4*)g_qn)[tid] = o;
}

// ---------------------------------------------------------------------------
// Kernel 2: fused scores + softmax-numerator + weighted-V accumulation.
// Head h of batch b uses contiguous region K[b] + h*S*D (flat .reshape view).
// Each block: one (chunk, h, b). 256 threads = 8 warps.
// Each warp iteration: 2 rows (lanes 0-15 row A, 16-31 row B), float4 per lane.
// K/V are streamed with __ldcs (evict-first) — never reused, keep L2 clean.
// ---------------------------------------------------------------------------
__global__ void __launch_bounds__(256) attn_partial_kernel(
    const float* __restrict__ K, const float* __restrict__ V) {
    const int c = blockIdx.x;   // S-chunk
    const int h = blockIdx.y;
    const int b = blockIdx.z;
    const int tid  = threadIdx.x;
    const int warp = tid >> 5;
    const int lane = tid & 31;

    const size_t base4 = (size_t)b * (S_ * C_ / 4) + (size_t)h * (S_ * D_ / 4)
                       + (size_t)c * (ROWS_PER_CHUNK * D_ / 4);
    const float4* __restrict__ K4 = (const float4*)K + base4;
    const float4* __restrict__ V4 = (const float4*)V + base4;

    const float4 q4 = ((const float4*)g_qn)[h * (D_ / 4) + (lane & 15)];

    float4 acc = make_float4(0.f, 0.f, 0.f, 0.f);
    float lsum = 0.f;

    // 256 rows / (2 rows per warp-iter) = 128 warp-iters / 8 warps = 16 iters
    #pragma unroll 8
    for (int i = 0; i < 16; i++) {
        const int idx = ((i << 3) + warp) * 32 + lane;   // contiguous 4KB per step across block
        float4 k = __ldcs(&K4[idx]);
        float4 v = __ldcs(&V4[idx]);
        float p = k.x*q4.x + k.y*q4.y + k.z*q4.z + k.w*q4.w;
        p += __shfl_xor_sync(0xFFFFFFFFu, p, 1);
        p += __shfl_xor_sync(0xFFFFFFFFu, p, 2);
        p += __shfl_xor_sync(0xFFFFFFFFu, p, 4);
        p += __shfl_xor_sync(0xFFFFFFFFu, p, 8);
        // scores ~ N(0, 0.03^2): exp without max-subtraction is exact + safe
        float w = __expf(p);
        lsum  += w;
        acc.x += w * v.x;
        acc.y += w * v.y;
        acc.z += w * v.z;
        acc.w += w * v.w;
    }

    // fold the two half-warps (rows) together: lane j (0-15) = cols 4j..4j+3
    acc.x += __shfl_xor_sync(0xFFFFFFFFu, acc.x, 16);
    acc.y += __shfl_xor_sync(0xFFFFFFFFu, acc.y, 16);
    acc.z += __shfl_xor_sync(0xFFFFFFFFu, acc.z, 16);
    acc.w += __shfl_xor_sync(0xFFFFFFFFu, acc.w, 16);
    lsum  += __shfl_xor_sync(0xFFFFFFFFu, lsum, 16);

    __shared__ float4 sacc[8][16];
    __shared__ float  sl[8];
    if (lane < 16) sacc[warp][lane] = acc;
    if (lane == 0) sl[warp] = lsum;
    __syncthreads();

    const int bh = b * H_ + h;
    if (tid < 16) {
        float4 s = make_float4(0.f, 0.f, 0.f, 0.f);
        #pragma unroll
        for (int w = 0; w < 8; w++) {
            float4 a = sacc[w][tid];
            s.x += a.x; s.y += a.y; s.z += a.z; s.w += a.w;
        }
        ((float4*)g_pacc)[(bh * SPLIT + c) * (D_ / 4) + tid] = s;
    } else if (tid == 16) {
        float L = 0.f;
        #pragma unroll
        for (int w = 0; w < 8; w++) L += sl[w];
        g_pl[bh * SPLIT + c] = L;
    }
}

// ---------------------------------------------------------------------------
// Kernel 3: combine chunk partials -> A[b, h*64+j] = (sum acc)/(sum l)
// ---------------------------------------------------------------------------
__global__ void combine_kernel() {
    int g = blockIdx.x * blockDim.x + threadIdx.x;   // 0..16383
    int bh = g >> 6;
    int j  = g & 63;
    float a = 0.f, L = 0.f;
    #pragma unroll
    for (int c = 0; c < SPLIT; c++) {
        a += g_pacc[(bh * SPLIT + c) * D_ + j];
        L += g_pl[bh * SPLIT + c];
    }
    g_A[g] = a / L;
}

// ---------------------------------------------------------------------------
// Kernel 4: k-split GEMM partials. Ypart[kc][b][n] = sum_{k in chunk} A[b][k]*w0[n][k]
// grid (16 n-tiles, 16 k-chunks) = 256 blocks, 256 threads = 64K threads.
// Thread: n_local = tid&63 (n = bx*64+n_local), bq = tid>>6 -> batches bq*4..bq*4+3.
// A chunk [16 b x 64 k] staged in smem (4KB). 16 float4 w0 loads/thread, full unroll.
// w0 comes cold from DRAM every iteration (evicted by the 512MB K/V stream):
// maximize thread count to cover latency with MLP.
// ---------------------------------------------------------------------------
__global__ void __launch_bounds__(256) gemm_partial_kernel(
    const float* __restrict__ w0w) {
    __shared__ float4 sA4[16 * 16];     // [b][kk4]: 16 batches x 16 float4 (64 k)
    const int tid = threadIdx.x;
    const int bx  = blockIdx.x;         // n-tile
    const int kc  = blockIdx.y;         // k-chunk

    // stage A: 256 float4 by 256 threads (1 each)
    {
        int b  = tid >> 4;              // 16 float4 per batch chunk
        int kk = tid & 15;
        sA4[tid] = ((const float4*)g_A)[b * 256 + kc * 16 + kk];
    }
    __syncthreads();

    const int n_local = tid & 63;
    const int bq      = tid >> 6;       // 0..3 -> batches bq*4..bq*4+3
    const int n       = bx * 64 + n_local;
    const float4* __restrict__ w4 = (const float4*)w0w + (size_t)n * 256 + kc * 16;

    float a0 = 0.f, a1 = 0.f, a2 = 0.f, a3 = 0.f;
    const float4* sA0 = &sA4[(bq * 4 + 0) * 16];
    const float4* sA1 = &sA4[(bq * 4 + 1) * 16];
    const float4* sA2 = &sA4[(bq * 4 + 2) * 16];
    const float4* sA3 = &sA4[(bq * 4 + 3) * 16];
    #pragma unroll
    for (int i = 0; i < 16; i++) {
        float4 wv = w4[i];
        float4 v0 = sA0[i];
        float4 v1 = sA1[i];
        float4 v2 = sA2[i];
        float4 v3 = sA3[i];
        a0 += wv.x*v0.x + wv.y*v0.y + wv.z*v0.z + wv.w*v0.w;
        a1 += wv.x*v1.x + wv.y*v1.y + wv.z*v1.z + wv.w*v1.w;
        a2 += wv.x*v2.x + wv.y*v2.y + wv.z*v2.z + wv.w*v2.w;
        a3 += wv.x*v3.x + wv.y*v3.y + wv.z*v3.z + wv.w*v3.w;
    }
    const size_t base = (size_t)kc * (B_ * C_);
    g_Ypart[base + (bq * 4 + 0) * C_ + n] = a0;
    g_Ypart[base + (bq * 4 + 1) * C_ + n] = a1;
    g_Ypart[base + (bq * 4 + 2) * C_ + n] = a2;
    g_Ypart[base + (bq * 4 + 3) * C_ + n] = a3;
}

// ---------------------------------------------------------------------------
// Kernel 5: combine GEMM partials + bias, then LayerNorm, write output.
// One block per batch, 256 threads, float4 each.
// ---------------------------------------------------------------------------
__global__ void __launch_bounds__(256) ln_kernel(
    const float* __restrict__ w0b,
    const float* __restrict__ lng, const float* __restrict__ lnb,
    float* __restrict__ out) {
    __shared__ float rsum[8], rsq[8];
    __shared__ float s_mu, s_rstd;
    const int b = blockIdx.x;
    const int tid = threadIdx.x;

    // y = bias + sum_kc Ypart[kc][b][tid*4..]
    float4 y = ((const float4*)w0b)[tid];
    #pragma unroll
    for (int kc = 0; kc < KSPLIT; kc++) {
        float4 p = ((const float4*)g_Ypart)[(size_t)kc * (B_ * C_ / 4) + b * 256 + tid];
        y.x += p.x; y.y += p.y; y.z += p.z; y.w += p.w;
    }

    float sm = y.x + y.y + y.z + y.w;
    float sq = y.x*y.x + y.y*y.y + y.z*y.z + y.w*y.w;
    #pragma unroll
    for (int o = 16; o; o >>= 1) {
        sm += __shfl_xor_sync(0xFFFFFFFFu, sm, o);
        sq += __shfl_xor_sync(0xFFFFFFFFu, sq, o);
    }
    if ((tid & 31) == 0) { rsum[tid >> 5] = sm; rsq[tid >> 5] = sq; }
    __syncthreads();
    if (tid == 0) {
        float ts = 0.f, tq = 0.f;
        #pragma unroll
        for (int w = 0; w < 8; w++) { ts += rsum[w]; tq += rsq[w]; }
        float mu  = ts * (1.0f / C_);
        float var = tq * (1.0f / C_) - mu * mu;
        s_mu   = mu;
        s_rstd = rsqrtf(var + 1e-5f);
    }
    __syncthreads();
    const float mu = s_mu, rstd = s_rstd;
    float4 g  = ((const float4*)lng)[tid];
    float4 be = ((const float4*)lnb)[tid];
    float4 o;
    o.x = g.x * (y.x - mu) * rstd + be.x;
    o.y = g.y * (y.y - mu) * rstd + be.y;
    o.z = g.z * (y.z - mu) * rstd + be.z;
    o.w = g.w * (y.w - mu) * rstd + be.w;
    ((float4*)out)[b * 256 + tid] = o;
}

// ---------------------------------------------------------------------------
extern "C" void kernel_launch(void* const* d_in, const int* in_sizes, int n_in,
                              void* d_out, int out_size) {
    const float* K   = (const float*)d_in[0];
    const float* V   = (const float*)d_in[1];
    const float* q   = (const float*)d_in[2];
    const float* w0w = (const float*)d_in[3];
    const float* w0b = (const float*)d_in[4];
    const float* lng = (const float*)d_in[5];
    const float* lnb = (const float*)d_in[6];
    float* out = (float*)d_out;

    qnorm_kernel<<<1, 256>>>(q);
    attn_partial_kernel<<<dim3(SPLIT, H_, B_), 256>>>(K, V);
    combine_kernel<<<64, 256>>>();
    gemm_partial_kernel<<<dim3(16, KSPLIT), 256>>>(w0w);
    ln_kernel<<<B_, 256>>>(w0b, lng, lnb, out);
}

// round 5
// speedup vs baseline: 1.0806x; 1.0806x over previous
#include <cuda_runtime.h>
#include <cuda_bf16.h>

// Problem constants
#define B_   16
#define S_   4096
#define C_   1024
#define H_   16
#define D_   64
#define SPLIT 8                       // S-chunks for attention (R2 best)
#define KSPLIT 16                     // k-chunks for the w0 GEMM == heads
#define NBH  (B_ * H_)                // 256
#define ROWS_PER_CHUNK (S_ / SPLIT)   // 512

// Scratch (device globals; no allocation allowed)
__device__ float g_qn[C_];                         // normalized*scaled query
__device__ float g_pacc[NBH * SPLIT * D_];         // partial weighted-V sums
__device__ float g_pl[NBH * SPLIT];                // partial exp-sums
__device__ float g_Ypart[KSPLIT * B_ * C_];        // GEMM k-chunk partials

// ---------------------------------------------------------------------------
// Kernel 1: qn = q / ||q|| * (1/sqrt(d))
// ---------------------------------------------------------------------------
__global__ void qnorm_kernel(const float* __restrict__ q) {
    __shared__ float red[8];
    __shared__ float s_scale;
    int tid = threadIdx.x;                 // 256 threads, 4 floats each
    float4 qv = ((const float4*)q)[tid];
    float s = qv.x*qv.x + qv.y*qv.y + qv.z*qv.z + qv.w*qv.w;
    #pragma unroll
    for (int o = 16; o; o >>= 1) s += __shfl_xor_sync(0xFFFFFFFFu, s, o);
    if ((tid & 31) == 0) red[tid >> 5] = s;
    __syncthreads();
    if (tid == 0) {
        float t = 0.f;
        #pragma unroll
        for (int w = 0; w < 8; w++) t += red[w];
        s_scale = rsqrtf(t) * 0.125f;      // 1/||q|| * 1/sqrt(64)
    }
    __syncthreads();
    float sc = s_scale;
    float4 o;
    o.x = qv.x * sc; o.y = qv.y * sc; o.z = qv.z * sc; o.w = qv.w * sc;
    ((float4*)g_qn)[tid] = o;
}

// ---------------------------------------------------------------------------
// Kernel 2: fused scores + softmax-numerator + weighted-V accumulation.
// Head h of batch b uses contiguous region K[b] + h*S*D (flat .reshape view).
// Each block: one (chunk, h, b). 256 threads = 8 warps.
// Each warp iteration: 2 rows (lanes 0-15 row A, 16-31 row B), float4 per lane.
// ---------------------------------------------------------------------------
__global__ void __launch_bounds__(256) attn_partial_kernel(
    const float* __restrict__ K, const float* __restrict__ V) {
    const int c = blockIdx.x;   // S-chunk
    const int h = blockIdx.y;
    const int b = blockIdx.z;
    const int tid  = threadIdx.x;
    const int warp = tid >> 5;
    const int lane = tid & 31;

    const size_t base4 = (size_t)b * (S_ * C_ / 4) + (size_t)h * (S_ * D_ / 4)
                       + (size_t)c * (ROWS_PER_CHUNK * D_ / 4);
    const float4* __restrict__ K4 = (const float4*)K + base4;
    const float4* __restrict__ V4 = (const float4*)V + base4;

    const float4 q4 = ((const float4*)g_qn)[h * (D_ / 4) + (lane & 15)];

    float4 acc = make_float4(0.f, 0.f, 0.f, 0.f);
    float lsum = 0.f;

    // 512 rows / (2 rows per warp-iter) = 256 warp-iters / 8 warps = 32 iters
    #pragma unroll 8
    for (int i = 0; i < 32; i++) {
        const int idx = ((i << 3) + warp) * 32 + lane;   // contiguous 4KB per step across block
        float4 k = K4[idx];
        float4 v = V4[idx];
        float p = k.x*q4.x + k.y*q4.y + k.z*q4.z + k.w*q4.w;
        p += __shfl_xor_sync(0xFFFFFFFFu, p, 1);
        p += __shfl_xor_sync(0xFFFFFFFFu, p, 2);
        p += __shfl_xor_sync(0xFFFFFFFFu, p, 4);
        p += __shfl_xor_sync(0xFFFFFFFFu, p, 8);
        // scores ~ N(0, 0.03^2): exp without max-subtraction is exact + safe
        float w = __expf(p);
        lsum  += w;
        acc.x += w * v.x;
        acc.y += w * v.y;
        acc.z += w * v.z;
        acc.w += w * v.w;
    }

    // fold the two half-warps (rows) together: lane j (0-15) = cols 4j..4j+3
    acc.x += __shfl_xor_sync(0xFFFFFFFFu, acc.x, 16);
    acc.y += __shfl_xor_sync(0xFFFFFFFFu, acc.y, 16);
    acc.z += __shfl_xor_sync(0xFFFFFFFFu, acc.z, 16);
    acc.w += __shfl_xor_sync(0xFFFFFFFFu, acc.w, 16);
    lsum  += __shfl_xor_sync(0xFFFFFFFFu, lsum, 16);

    __shared__ float4 sacc[8][16];
    __shared__ float  sl[8];
    if (lane < 16) sacc[warp][lane] = acc;
    if (lane == 0) sl[warp] = lsum;
    __syncthreads();

    const int bh = b * H_ + h;
    if (tid < 16) {
        float4 s = make_float4(0.f, 0.f, 0.f, 0.f);
        #pragma unroll
        for (int w = 0; w < 8; w++) {
            float4 a = sacc[w][tid];
            s.x += a.x; s.y += a.y; s.z += a.z; s.w += a.w;
        }
        ((float4*)g_pacc)[(bh * SPLIT + c) * (D_ / 4) + tid] = s;
    } else if (tid == 16) {
        float L = 0.f;
        #pragma unroll
        for (int w = 0; w < 8; w++) L += sl[w];
        g_pl[bh * SPLIT + c] = L;
    }
}

// ---------------------------------------------------------------------------
// Kernel 3: fused combine + k-split GEMM.
// KSPLIT == H_, so k-chunk h covers exactly head h's 64 columns of A.
// Block (bx = n-tile, h). 256 threads.
// Order: (1) issue all 16 float4 w0 loads into registers (cold DRAM, deep MLP),
//        (2) build A chunk from g_pacc/g_pl partials (L2-hot) into smem,
//        (3) syncthreads, FMA from registers + smem. No exposed latency in (3).
// ---------------------------------------------------------------------------
__global__ void __launch_bounds__(256) gemm_fused_kernel(
    const float* __restrict__ w0w) {
    __shared__ float4 sA4[16 * 16];     // [b][j4]: 16 batches x 16 float4 (64 k of head h)
    const int tid = threadIdx.x;
    const int bx  = blockIdx.x;         // n-tile
    const int h   = blockIdx.y;         // head == k-chunk
    const int n_local = tid & 63;
    const int bq      = tid >> 6;       // 0..3 -> batches bq*4..bq*4+3
    const int n       = bx * 64 + n_local;

    // (1) prefetch w0 row chunk into registers — pure LDG burst
    const float4* __restrict__ w4 = (const float4*)w0w + (size_t)n * 256 + h * 16;
    float4 wv[16];
    #pragma unroll
    for (int i = 0; i < 16; i++) wv[i] = w4[i];

    // (2) combine staging: thread -> b = tid>>4, j4 = tid&15
    {
        const int b  = tid >> 4;
        const int j4 = tid & 15;
        const int bh = b * H_ + h;
        float L = 0.f;
        #pragma unroll
        for (int c = 0; c < SPLIT; c++) L += g_pl[bh * SPLIT + c];
        float4 s = make_float4(0.f, 0.f, 0.f, 0.f);
        #pragma unroll
        for (int c = 0; c < SPLIT; c++) {
            float4 p = ((const float4*)g_pacc)[(bh * SPLIT + c) * 16 + j4];
            s.x += p.x; s.y += p.y; s.z += p.z; s.w += p.w;
        }
        const float inv = 1.0f / L;
        s.x *= inv; s.y *= inv; s.z *= inv; s.w *= inv;
        sA4[tid] = s;
    }
    __syncthreads();

    // (3) FMA: 4 batches per thread
    float a0 = 0.f, a1 = 0.f, a2 = 0.f, a3 = 0.f;
    const float4* sA0 = &sA4[(bq * 4 + 0) * 16];
    const float4* sA1 = &sA4[(bq * 4 + 1) * 16];
    const float4* sA2 = &sA4[(bq * 4 + 2) * 16];
    const float4* sA3 = &sA4[(bq * 4 + 3) * 16];
    #pragma unroll
    for (int i = 0; i < 16; i++) {
        float4 w  = wv[i];
        float4 v0 = sA0[i];
        float4 v1 = sA1[i];
        float4 v2 = sA2[i];
        float4 v3 = sA3[i];
        a0 += w.x*v0.x + w.y*v0.y + w.z*v0.z + w.w*v0.w;
        a1 += w.x*v1.x + w.y*v1.y + w.z*v1.z + w.w*v1.w;
        a2 += w.x*v2.x + w.y*v2.y + w.z*v2.z + w.w*v2.w;
        a3 += w.x*v3.x + w.y*v3.y + w.z*v3.z + w.w*v3.w;
    }
    const size_t base = (size_t)h * (B_ * C_);
    g_Ypart[base + (bq * 4 + 0) * C_ + n] = a0;
    g_Ypart[base + (bq * 4 + 1) * C_ + n] = a1;
    g_Ypart[base + (bq * 4 + 2) * C_ + n] = a2;
    g_Ypart[base + (bq * 4 + 3) * C_ + n] = a3;
}

// ---------------------------------------------------------------------------
// Kernel 4: combine GEMM partials + bias, then LayerNorm, write output.
// One block per batch, 256 threads, float4 each.
// ---------------------------------------------------------------------------
__global__ void __launch_bounds__(256) ln_kernel(
    const float* __restrict__ w0b,
    const float* __restrict__ lng, const float* __restrict__ lnb,
    float* __restrict__ out) {
    __shared__ float rsum[8], rsq[8];
    __shared__ float s_mu, s_rstd;
    const int b = blockIdx.x;
    const int tid = threadIdx.x;

    // y = bias + sum_kc Ypart[kc][b][tid*4..]
    float4 y = ((const float4*)w0b)[tid];
    #pragma unroll
    for (int kc = 0; kc < KSPLIT; kc++) {
        float4 p = ((const float4*)g_Ypart)[(size_t)kc * (B_ * C_ / 4) + b * 256 + tid];
        y.x += p.x; y.y += p.y; y.z += p.z; y.w += p.w;
    }

    float sm = y.x + y.y + y.z + y.w;
    float sq = y.x*y.x + y.y*y.y + y.z*y.z + y.w*y.w;
    #pragma unroll
    for (int o = 16; o; o >>= 1) {
        sm += __shfl_xor_sync(0xFFFFFFFFu, sm, o);
        sq += __shfl_xor_sync(0xFFFFFFFFu, sq, o);
    }
    if ((tid & 31) == 0) { rsum[tid >> 5] = sm; rsq[tid >> 5] = sq; }
    __syncthreads();
    if (tid == 0) {
        float ts = 0.f, tq = 0.f;
        #pragma unroll
        for (int w = 0; w < 8; w++) { ts += rsum[w]; tq += rsq[w]; }
        float mu  = ts * (1.0f / C_);
        float var = tq * (1.0f / C_) - mu * mu;
        s_mu   = mu;
        s_rstd = rsqrtf(var + 1e-5f);
    }
    __syncthreads();
    const float mu = s_mu, rstd = s_rstd;
    float4 g  = ((const float4*)lng)[tid];
    float4 be = ((const float4*)lnb)[tid];
    float4 o;
    o.x = g.x * (y.x - mu) * rstd + be.x;
    o.y = g.y * (y.y - mu) * rstd + be.y;
    o.z = g.z * (y.z - mu) * rstd + be.z;
    o.w = g.w * (y.w - mu) * rstd + be.w;
    ((float4*)out)[b * 256 + tid] = o;
}

// ---------------------------------------------------------------------------
extern "C" void kernel_launch(void* const* d_in, const int* in_sizes, int n_in,
                              void* d_out, int out_size) {
    const float* K   = (const float*)d_in[0];
    const float* V   = (const float*)d_in[1];
    const float* q   = (const float*)d_in[2];
    const float* w0w = (const float*)d_in[3];
    const float* w0b = (const float*)d_in[4];
    const float* lng = (const float*)d_in[5];
    const float* lnb = (const float*)d_in[6];
    float* out = (float*)d_out;

    qnorm_kernel<<<1, 256>>>(q);
    attn_partial_kernel<<<dim3(SPLIT, H_, B_), 256>>>(K, V);
    gemm_fused_kernel<<<dim3(16, KSPLIT), 256>>>(w0w);
    ln_kernel<<<B_, 256>>>(w0b, lng, lnb, out);
}

// round 6
// speedup vs baseline: 1.0836x; 1.0028x over previous
#include <cuda_runtime.h>
#include <cuda_bf16.h>

// Problem constants
#define B_   16
#define S_   4096
#define C_   1024
#define H_   16
#define D_   64
#define SPLIT 8                       // S-chunks for attention (measured best)
#define KSPLIT 16                     // k-chunks for the w0 GEMM == heads
#define NBH  (B_ * H_)                // 256
#define ROWS_PER_CHUNK (S_ / SPLIT)   // 512

// Scratch (device globals; no allocation allowed)
__device__ float g_qn[C_];                         // normalized*scaled query
__device__ float g_pacc[NBH * SPLIT * D_];         // partial weighted-V sums
__device__ float g_pl[NBH * SPLIT];                // partial exp-sums
__device__ float g_Ypart[KSPLIT * B_ * C_];        // GEMM k-chunk partials

// ---------------------------------------------------------------------------
// Kernel 1: qn = q / ||q|| * (1/sqrt(d))
// ---------------------------------------------------------------------------
__global__ void qnorm_kernel(const float* __restrict__ q) {
    __shared__ float red[8];
    __shared__ float s_scale;
    int tid = threadIdx.x;                 // 256 threads, 4 floats each
    float4 qv = ((const float4*)q)[tid];
    float s = qv.x*qv.x + qv.y*qv.y + qv.z*qv.z + qv.w*qv.w;
    #pragma unroll
    for (int o = 16; o; o >>= 1) s += __shfl_xor_sync(0xFFFFFFFFu, s, o);
    if ((tid & 31) == 0) red[tid >> 5] = s;
    __syncthreads();
    if (tid == 0) {
        float t = 0.f;
        #pragma unroll
        for (int w = 0; w < 8; w++) t += red[w];
        s_scale = rsqrtf(t) * 0.125f;      // 1/||q|| * 1/sqrt(64)
    }
    __syncthreads();
    float sc = s_scale;
    float4 o;
    o.x = qv.x * sc; o.y = qv.y * sc; o.z = qv.z * sc; o.w = qv.w * sc;
    ((float4*)g_qn)[tid] = o;
}

// ---------------------------------------------------------------------------
// Kernel 2: fused scores + softmax-numerator + weighted-V accumulation.
// Head h of batch b uses contiguous region K[b] + h*S*D (flat .reshape view).
// Each block: one (chunk, h, b). 256 threads = 8 warps.
// Each warp iteration: 2 rows (lanes 0-15 row A, 16-31 row B), float4 per lane.
// ---------------------------------------------------------------------------
__global__ void __launch_bounds__(256) attn_partial_kernel(
    const float* __restrict__ K, const float* __restrict__ V) {
    const int c = blockIdx.x;   // S-chunk
    const int h = blockIdx.y;
    const int b = blockIdx.z;
    const int tid  = threadIdx.x;
    const int warp = tid >> 5;
    const int lane = tid & 31;

    const size_t base4 = (size_t)b * (S_ * C_ / 4) + (size_t)h * (S_ * D_ / 4)
                       + (size_t)c * (ROWS_PER_CHUNK * D_ / 4);
    const float4* __restrict__ K4 = (const float4*)K + base4;
    const float4* __restrict__ V4 = (const float4*)V + base4;

    const float4 q4 = ((const float4*)g_qn)[h * (D_ / 4) + (lane & 15)];

    float4 acc = make_float4(0.f, 0.f, 0.f, 0.f);
    float lsum = 0.f;

    // 512 rows / (2 rows per warp-iter) = 256 warp-iters / 8 warps = 32 iters
    #pragma unroll 8
    for (int i = 0; i < 32; i++) {
        const int idx = ((i << 3) + warp) * 32 + lane;   // contiguous 4KB per step across block
        float4 k = K4[idx];
        float4 v = V4[idx];
        float p = k.x*q4.x + k.y*q4.y + k.z*q4.z + k.w*q4.w;
        p += __shfl_xor_sync(0xFFFFFFFFu, p, 1);
        p += __shfl_xor_sync(0xFFFFFFFFu, p, 2);
        p += __shfl_xor_sync(0xFFFFFFFFu, p, 4);
        p += __shfl_xor_sync(0xFFFFFFFFu, p, 8);
        // scores ~ N(0, 0.03^2): exp without max-subtraction is exact + safe
        float w = __expf(p);
        lsum  += w;
        acc.x += w * v.x;
        acc.y += w * v.y;
        acc.z += w * v.z;
        acc.w += w * v.w;
    }

    // fold the two half-warps (rows) together: lane j (0-15) = cols 4j..4j+3
    acc.x += __shfl_xor_sync(0xFFFFFFFFu, acc.x, 16);
    acc.y += __shfl_xor_sync(0xFFFFFFFFu, acc.y, 16);
    acc.z += __shfl_xor_sync(0xFFFFFFFFu, acc.z, 16);
    acc.w += __shfl_xor_sync(0xFFFFFFFFu, acc.w, 16);
    lsum  += __shfl_xor_sync(0xFFFFFFFFu, lsum, 16);

    __shared__ float4 sacc[8][16];
    __shared__ float  sl[8];
    if (lane < 16) sacc[warp][lane] = acc;
    if (lane == 0) sl[warp] = lsum;
    __syncthreads();

    const int bh = b * H_ + h;
    if (tid < 16) {
        float4 s = make_float4(0.f, 0.f, 0.f, 0.f);
        #pragma unroll
        for (int w = 0; w < 8; w++) {
            float4 a = sacc[w][tid];
            s.x += a.x; s.y += a.y; s.z += a.z; s.w += a.w;
        }
        ((float4*)g_pacc)[(bh * SPLIT + c) * (D_ / 4) + tid] = s;
    } else if (tid == 16) {
        float L = 0.f;
        #pragma unroll
        for (int w = 0; w < 8; w++) L += sl[w];
        g_pl[bh * SPLIT + c] = L;
    }
}

// ---------------------------------------------------------------------------
// Kernel 3: fused combine + k-split GEMM.
// KSPLIT == H_, so k-chunk h covers exactly head h's 64 columns of A.
// Block (bx = n-tile, h). 256 threads.
// Order: (1) issue all 16 float4 w0 loads into registers (cold DRAM, deep MLP),
//        (2) build A chunk from g_pacc/g_pl partials (L2-hot) into smem,
//        (3) syncthreads, FMA from registers + smem. No exposed latency in (3).
// ---------------------------------------------------------------------------
__global__ void __launch_bounds__(256) gemm_fused_kernel(
    const float* __restrict__ w0w) {
    __shared__ float4 sA4[16 * 16];     // [b][j4]: 16 batches x 16 float4 (64 k of head h)
    const int tid = threadIdx.x;
    const int bx  = blockIdx.x;         // n-tile
    const int h   = blockIdx.y;         // head == k-chunk
    const int n_local = tid & 63;
    const int bq      = tid >> 6;       // 0..3 -> batches bq*4..bq*4+3
    const int n       = bx * 64 + n_local;

    // (1) prefetch w0 row chunk into registers — pure LDG burst
    const float4* __restrict__ w4 = (const float4*)w0w + (size_t)n * 256 + h * 16;
    float4 wv[16];
    #pragma unroll
    for (int i = 0; i < 16; i++) wv[i] = w4[i];

    // (2) combine staging: thread -> b = tid>>4, j4 = tid&15
    {
        const int b  = tid >> 4;
        const int j4 = tid & 15;
        const int bh = b * H_ + h;
        float L = 0.f;
        #pragma unroll
        for (int c = 0; c < SPLIT; c++) L += g_pl[bh * SPLIT + c];
        float4 s = make_float4(0.f, 0.f, 0.f, 0.f);
        #pragma unroll
        for (int c = 0; c < SPLIT; c++) {
            float4 p = ((const float4*)g_pacc)[(bh * SPLIT + c) * 16 + j4];
            s.x += p.x; s.y += p.y; s.z += p.z; s.w += p.w;
        }
        const float inv = 1.0f / L;
        s.x *= inv; s.y *= inv; s.z *= inv; s.w *= inv;
        sA4[tid] = s;
    }
    __syncthreads();

    // (3) FMA: 4 batches per thread
    float a0 = 0.f, a1 = 0.f, a2 = 0.f, a3 = 0.f;
    const float4* sA0 = &sA4[(bq * 4 + 0) * 16];
    const float4* sA1 = &sA4[(bq * 4 + 1) * 16];
    const float4* sA2 = &sA4[(bq * 4 + 2) * 16];
    const float4* sA3 = &sA4[(bq * 4 + 3) * 16];
    #pragma unroll
    for (int i = 0; i < 16; i++) {
        float4 w  = wv[i];
        float4 v0 = sA0[i];
        float4 v1 = sA1[i];
        float4 v2 = sA2[i];
        float4 v3 = sA3[i];
        a0 += w.x*v0.x + w.y*v0.y + w.z*v0.z + w.w*v0.w;
        a1 += w.x*v1.x + w.y*v1.y + w.z*v1.z + w.w*v1.w;
        a2 += w.x*v2.x + w.y*v2.y + w.z*v2.z + w.w*v2.w;
        a3 += w.x*v3.x + w.y*v3.y + w.z*v3.z + w.w*v3.w;
    }
    const size_t base = (size_t)h * (B_ * C_);
    g_Ypart[base + (bq * 4 + 0) * C_ + n] = a0;
    g_Ypart[base + (bq * 4 + 1) * C_ + n] = a1;
    g_Ypart[base + (bq * 4 + 2) * C_ + n] = a2;
    g_Ypart[base + (bq * 4 + 3) * C_ + n] = a3;
}

// ---------------------------------------------------------------------------
// Kernel 4: combine GEMM partials + bias, then LayerNorm, write output.
// One block per batch, 1024 threads.
// Thread t: group g = t>>8 (sums k-chunks 4g..4g+3), n4 = t&255.
// Group partials combined through smem; first 256 threads finish stats+write.
// ---------------------------------------------------------------------------
__global__ void __launch_bounds__(1024) ln_kernel(
    const float* __restrict__ w0b,
    const float* __restrict__ lng, const float* __restrict__ lnb,
    float* __restrict__ out) {
    __shared__ float4 sY[4 * 256];      // [group][n4]
    __shared__ float rsum[8], rsq[8];
    __shared__ float s_mu, s_rstd;
    const int b   = blockIdx.x;
    const int tid = threadIdx.x;
    const int g   = tid >> 8;           // 0..3
    const int n4  = tid & 255;

    // each thread sums 4 k-chunk partials (4x the in-flight loads vs 16-deep chain)
    float4 p = make_float4(0.f, 0.f, 0.f, 0.f);
    #pragma unroll
    for (int j = 0; j < 4; j++) {
        const int kc = g * 4 + j;
        float4 t = ((const float4*)g_Ypart)[(size_t)kc * (B_ * C_ / 4) + b * 256 + n4];
        p.x += t.x; p.y += t.y; p.z += t.z; p.w += t.w;
    }
    sY[g * 256 + n4] = p;
    __syncthreads();

    float4 y;
    if (tid < 256) {
        y = ((const float4*)w0b)[tid];
        #pragma unroll
        for (int gg = 0; gg < 4; gg++) {
            float4 t = sY[gg * 256 + tid];
            y.x += t.x; y.y += t.y; y.z += t.z; y.w += t.w;
        }
        float sm = y.x + y.y + y.z + y.w;
        float sq = y.x*y.x + y.y*y.y + y.z*y.z + y.w*y.w;
        #pragma unroll
        for (int o = 16; o; o >>= 1) {
            sm += __shfl_xor_sync(0xFFFFFFFFu, sm, o);
            sq += __shfl_xor_sync(0xFFFFFFFFu, sq, o);
        }
        if ((tid & 31) == 0) { rsum[tid >> 5] = sm; rsq[tid >> 5] = sq; }
    }
    __syncthreads();
    if (tid == 0) {
        float ts = 0.f, tq = 0.f;
        #pragma unroll
        for (int w = 0; w < 8; w++) { ts += rsum[w]; tq += rsq[w]; }
        float mu  = ts * (1.0f / C_);
        float var = tq * (1.0f / C_) - mu * mu;
        s_mu   = mu;
        s_rstd = rsqrtf(var + 1e-5f);
    }
    __syncthreads();
    if (tid < 256) {
        const float mu = s_mu, rstd = s_rstd;
        float4 gm = ((const float4*)lng)[tid];
        float4 be = ((const float4*)lnb)[tid];
        float4 o;
        o.x = gm.x * (y.x - mu) * rstd + be.x;
        o.y = gm.y * (y.y - mu) * rstd + be.y;
        o.z = gm.z * (y.z - mu) * rstd + be.z;
        o.w = gm.w * (y.w - mu) * rstd + be.w;
        ((float4*)out)[b * 256 + tid] = o;
    }
}

// ---------------------------------------------------------------------------
extern "C" void kernel_launch(void* const* d_in, const int* in_sizes, int n_in,
                              void* d_out, int out_size) {
    const float* K   = (const float*)d_in[0];
    const float* V   = (const float*)d_in[1];
    const float* q   = (const float*)d_in[2];
    const float* w0w = (const float*)d_in[3];
    const float* w0b = (const float*)d_in[4];
    const float* lng = (const float*)d_in[5];
    const float* lnb = (const float*)d_in[6];
    float* out = (float*)d_out;

    qnorm_kernel<<<1, 256>>>(q);
    attn_partial_kernel<<<dim3(SPLIT, H_, B_), 256>>>(K, V);
    gemm_fused_kernel<<<dim3(16, KSPLIT), 256>>>(w0w);
    ln_kernel<<<B_, 1024>>>(w0b, lng, lnb, out);
}